// round 2
// baseline (speedup 1.0000x reference)
#include <cuda_runtime.h>
#include <cstdint>

#define N_NODES 100000
#define D_IN    256
#define D_HID   128
#define N_CLS   47
#define NC_PAD  48

// ---- scratch (static device globals; no allocation allowed) ----
__device__ __align__(16) float g_deg [N_NODES];
__device__ __align__(16) float g_dinv[N_NODES];
__device__ __align__(16) float g_h   [(size_t)N_NODES * D_HID];   // h_scaled = (x@W1)*dinv[row]
__device__ __align__(16) float g_agg [(size_t)N_NODES * D_HID];   // layer-1 aggregation
__device__ __align__(16) float g_h2  [(size_t)N_NODES * NC_PAD];  // h2_scaled, padded to 48
__device__ __align__(16) float g_agg2[(size_t)N_NODES * NC_PAD];  // layer-2 aggregation

// ---------------------------------------------------------------
__global__ void k_init_deg() {
    int i = blockIdx.x * blockDim.x + threadIdx.x;
    if (i < N_NODES) g_deg[i] = 1.0f;           // self-loop
}

__global__ void k_deg_scatter(const int* __restrict__ dst, int E) {
    int e = blockIdx.x * blockDim.x + threadIdx.x;
    if (e < E) atomicAdd(&g_deg[dst[e]], 1.0f);
}

__global__ void k_dinv() {
    int i = blockIdx.x * blockDim.x + threadIdx.x;
    if (i < N_NODES) g_dinv[i] = rsqrtf(g_deg[i]);
}

// ---------------------------------------------------------------
// GEMM1: h_scaled[row][c] = dinv[row] * sum_k x[row][k]*W1[k][c]
// Writes g_h and g_agg (self-loop init) simultaneously.
// BM=64, BN=128, BK=16, 128 threads, 8x8 per thread.
__global__ __launch_bounds__(128) void k_gemm1(const float* __restrict__ x,
                                               const float* __restrict__ W1) {
    __shared__ __align__(16) float As[64][16];
    __shared__ __align__(16) float Bs[16][128];
    const int tid  = threadIdx.x;
    const int row0 = blockIdx.x * 64;
    const int tcol = tid & 15;   // 16 col-threads * 8 cols
    const int trow = tid >> 4;   // 8 row-threads  * 8 rows

    float acc[8][8];
#pragma unroll
    for (int i = 0; i < 8; i++)
#pragma unroll
        for (int j = 0; j < 8; j++) acc[i][j] = 0.0f;

    for (int kt = 0; kt < D_IN / 16; kt++) {
        // A tile: 64x16 = 256 float4 slots
#pragma unroll
        for (int t = tid; t < 256; t += 128) {
            int r = t >> 2, c = t & 3;
            int row = row0 + r;
            float4 v = make_float4(0.f, 0.f, 0.f, 0.f);
            if (row < N_NODES)
                v = *(const float4*)&x[(size_t)row * D_IN + kt * 16 + c * 4];
            As[r][c * 4 + 0] = v.x; As[r][c * 4 + 1] = v.y;
            As[r][c * 4 + 2] = v.z; As[r][c * 4 + 3] = v.w;
        }
        // B tile: 16x128 = 512 float4 slots
#pragma unroll
        for (int t = tid; t < 512; t += 128) {
            int r = t >> 5, c = t & 31;
            float4 v = *(const float4*)&W1[(size_t)(kt * 16 + r) * D_HID + c * 4];
            *(float4*)&Bs[r][c * 4] = v;
        }
        __syncthreads();
#pragma unroll
        for (int kk = 0; kk < 16; kk++) {
            float a[8];
#pragma unroll
            for (int i = 0; i < 8; i++) a[i] = As[trow * 8 + i][kk];
            float4 b0 = *(const float4*)&Bs[kk][tcol * 8];
            float4 b1 = *(const float4*)&Bs[kk][tcol * 8 + 4];
            float b[8] = {b0.x, b0.y, b0.z, b0.w, b1.x, b1.y, b1.z, b1.w};
#pragma unroll
            for (int i = 0; i < 8; i++)
#pragma unroll
                for (int j = 0; j < 8; j++) acc[i][j] = fmaf(a[i], b[j], acc[i][j]);
        }
        __syncthreads();
    }

#pragma unroll
    for (int i = 0; i < 8; i++) {
        int row = row0 + trow * 8 + i;
        if (row < N_NODES) {
            float dv = g_dinv[row];
            float4 v0 = make_float4(acc[i][0] * dv, acc[i][1] * dv,
                                    acc[i][2] * dv, acc[i][3] * dv);
            float4 v1 = make_float4(acc[i][4] * dv, acc[i][5] * dv,
                                    acc[i][6] * dv, acc[i][7] * dv);
            size_t base = (size_t)row * D_HID + tcol * 8;
            *(float4*)&g_h[base]       = v0;
            *(float4*)&g_h[base + 4]   = v1;
            *(float4*)&g_agg[base]     = v0;   // self-loop contribution
            *(float4*)&g_agg[base + 4] = v1;
        }
    }
}

// ---------------------------------------------------------------
// Scatter layer 1: one float4 chunk per thread (32 chunks/edge -> warp/edge)
__global__ void k_scatter1(const int* __restrict__ src,
                           const int* __restrict__ dst, int E) {
    int idx = blockIdx.x * blockDim.x + threadIdx.x;
    if (idx >= E * 32) return;
    int e = idx >> 5, c = idx & 31;
    int s = src[e];
    int d = dst[e];
    float4 v = *(const float4*)&g_h[(size_t)s * D_HID + c * 4];
    float* ap = &g_agg[(size_t)d * D_HID + c * 4];
    atomicAdd(ap + 0, v.x);
    atomicAdd(ap + 1, v.y);
    atomicAdd(ap + 2, v.z);
    atomicAdd(ap + 3, v.w);
}

// ---------------------------------------------------------------
// GEMM2 fused: A[row][k] = relu(dinv[row]*g_agg[row][k] + b1[k]), B = W2 (pad 48)
// out: g_h2 = g_agg2 = dinv[row] * (A @ W2)
// BM=64, BN=48, K=128 tiled BK=32, 256 threads, 4x3 per thread.
__global__ __launch_bounds__(256) void k_gemm2(const float* __restrict__ b1,
                                               const float* __restrict__ W2) {
    __shared__ __align__(16) float As[64][32];
    __shared__ __align__(16) float Bs[D_HID][NC_PAD];
    __shared__ __align__(16) float b1s[D_HID];
    const int tid  = threadIdx.x;
    const int row0 = blockIdx.x * 64;
    const int tcol = tid & 15;   // cols tcol*3 .. +2
    const int trow = tid >> 4;   // rows trow*4 .. +3

    if (tid < D_HID) b1s[tid] = b1[tid];
    for (int t = tid; t < D_HID * NC_PAD; t += 256) {
        int r = t / NC_PAD, c = t % NC_PAD;
        Bs[r][c] = (c < N_CLS) ? W2[(size_t)r * N_CLS + c] : 0.0f;
    }
    __syncthreads();

    float acc[4][3];
#pragma unroll
    for (int i = 0; i < 4; i++)
#pragma unroll
        for (int j = 0; j < 3; j++) acc[i][j] = 0.0f;

    for (int kt = 0; kt < 4; kt++) {
        // A tile: 64x32 = 512 float4 slots, finalize fused
#pragma unroll
        for (int t = tid; t < 512; t += 256) {
            int r = t >> 3, c = t & 7;
            int row = row0 + r;
            float4 h = make_float4(0.f, 0.f, 0.f, 0.f);
            if (row < N_NODES) {
                float dv = g_dinv[row];
                float4 a  = *(const float4*)&g_agg[(size_t)row * D_HID + kt * 32 + c * 4];
                float4 bb = *(const float4*)&b1s[kt * 32 + c * 4];
                h.x = fmaxf(fmaf(dv, a.x, bb.x), 0.f);
                h.y = fmaxf(fmaf(dv, a.y, bb.y), 0.f);
                h.z = fmaxf(fmaf(dv, a.z, bb.z), 0.f);
                h.w = fmaxf(fmaf(dv, a.w, bb.w), 0.f);
            }
            As[r][c * 4 + 0] = h.x; As[r][c * 4 + 1] = h.y;
            As[r][c * 4 + 2] = h.z; As[r][c * 4 + 3] = h.w;
        }
        __syncthreads();
#pragma unroll
        for (int kk = 0; kk < 32; kk++) {
            float a[4], b[3];
#pragma unroll
            for (int i = 0; i < 4; i++) a[i] = As[trow * 4 + i][kk];
#pragma unroll
            for (int j = 0; j < 3; j++) b[j] = Bs[kt * 32 + kk][tcol * 3 + j];
#pragma unroll
            for (int i = 0; i < 4; i++)
#pragma unroll
                for (int j = 0; j < 3; j++) acc[i][j] = fmaf(a[i], b[j], acc[i][j]);
        }
        __syncthreads();
    }

#pragma unroll
    for (int i = 0; i < 4; i++) {
        int row = row0 + trow * 4 + i;
        if (row < N_NODES) {
            float dv = g_dinv[row];
#pragma unroll
            for (int j = 0; j < 3; j++) {
                int col = tcol * 3 + j;
                float v = acc[i][j] * dv;
                g_h2  [(size_t)row * NC_PAD + col] = v;
                g_agg2[(size_t)row * NC_PAD + col] = v;   // self-loop init
            }
        }
    }
}

// ---------------------------------------------------------------
// Scatter layer 2: 12 float4 chunks per edge (48 padded floats)
__global__ void k_scatter2(const int* __restrict__ src,
                           const int* __restrict__ dst, int E) {
    int idx = blockIdx.x * blockDim.x + threadIdx.x;
    if (idx >= E * 12) return;
    int e = idx / 12, c = idx % 12;
    int s = src[e];
    int d = dst[e];
    float4 v = *(const float4*)&g_h2[(size_t)s * NC_PAD + c * 4];
    float* ap = &g_agg2[(size_t)d * NC_PAD + c * 4];
    atomicAdd(ap + 0, v.x);
    atomicAdd(ap + 1, v.y);
    atomicAdd(ap + 2, v.z);
    atomicAdd(ap + 3, v.w);
}

// ---------------------------------------------------------------
__global__ void k_finalize2(const float* __restrict__ b2, float* __restrict__ out) {
    int idx = blockIdx.x * blockDim.x + threadIdx.x;
    if (idx >= N_NODES * N_CLS) return;
    int i = idx / N_CLS, j = idx - i * N_CLS;
    out[idx] = g_dinv[i] * g_agg2[(size_t)i * NC_PAD + j] + b2[j];
}

// ---------------------------------------------------------------
extern "C" void kernel_launch(void* const* d_in, const int* in_sizes, int n_in,
                              void* d_out, int out_size) {
    const float* x    = (const float*)d_in[0];
    const int*   edge = (const int*)d_in[1];     // int32! (JAX default x64-disabled)
    const float* W1   = (const float*)d_in[2];
    const float* b1   = (const float*)d_in[3];
    const float* W2   = (const float*)d_in[4];
    const float* b2   = (const float*)d_in[5];
    float*       out  = (float*)d_out;

    const int E = in_sizes[1] / 2;
    const int* src = edge;
    const int* dst = edge + E;

    k_init_deg   <<<(N_NODES + 255) / 256, 256>>>();
    k_deg_scatter<<<(E + 255) / 256, 256>>>(dst, E);
    k_dinv       <<<(N_NODES + 255) / 256, 256>>>();

    k_gemm1      <<<(N_NODES + 63) / 64, 128>>>(x, W1);

    int w1 = E * 32;
    k_scatter1   <<<(w1 + 255) / 256, 256>>>(src, dst, E);

    k_gemm2      <<<(N_NODES + 63) / 64, 256>>>(b1, W2);

    int w2 = E * 12;
    k_scatter2   <<<(w2 + 255) / 256, 256>>>(src, dst, E);

    int w3 = N_NODES * N_CLS;
    k_finalize2  <<<(w3 + 255) / 256, 256>>>(b2, out);
}

// round 3
// speedup vs baseline: 2.1037x; 2.1037x over previous
#include <cuda_runtime.h>
#include <cstdint>

#define N_NODES 100000
#define N_EDGES 1600000
#define D_IN    256
#define D_HID   128
#define N_CLS   47
#define NC_PAD  48
#define NBLK_SCAN ((N_NODES + 255) / 256)   // 391

// ---- scratch (static device globals) ----
__device__ __align__(16) float g_dinv[N_NODES];
__device__ int   g_cnt[N_NODES];
__device__ int   g_cur[N_NODES];
__device__ int   g_off[N_NODES + 1];
__device__ int   g_bsum[NBLK_SCAN];
__device__ int   g_bbase[NBLK_SCAN];
__device__ int   g_csr[N_EDGES];
__device__ __align__(16) float g_h [(size_t)N_NODES * D_HID];   // dinv[r]*(x@W1)
__device__ __align__(16) float g_h1[(size_t)N_NODES * D_HID];   // relu(gcn1)
__device__ __align__(16) float g_h2[(size_t)N_NODES * NC_PAD];  // dinv[r]*(h1@W2), pad 48

// ---- f32x2 packed-FMA helpers ----
#define FMA_F32X2(d, a, b) \
    asm("fma.rn.f32x2 %0, %1, %2, %0;" : "+l"(d) : "l"(a), "l"(b))
#define PK_DUP(dst, f) \
    asm("mov.b64 %0, {%1, %1};" : "=l"(dst) : "r"(__float_as_uint(f)))
#define UNPK(lo, hi, v) \
    asm("mov.b64 {%0, %1}, %2;" : "=r"(lo), "=r"(hi) : "l"(v))

// ---------------------------------------------------------------
__global__ void k_init() {
    int i = blockIdx.x * blockDim.x + threadIdx.x;
    if (i < N_NODES) { g_cnt[i] = 0; g_cur[i] = 0; }
}

__global__ void k_count(const int* __restrict__ dst, int E) {
    int e = blockIdx.x * blockDim.x + threadIdx.x;
    if (e < E) atomicAdd(&g_cnt[dst[e]], 1);
}

__global__ void k_dinv() {
    int i = blockIdx.x * blockDim.x + threadIdx.x;
    if (i < N_NODES) g_dinv[i] = rsqrtf((float)g_cnt[i] + 1.0f);  // +1 self-loop
}

// ---- 3-phase exclusive prefix sum of g_cnt -> g_off ----
__global__ void k_scan_block() {
    __shared__ int s[256];
    int i = blockIdx.x * 256 + threadIdx.x;
    int t = threadIdx.x;
    s[t] = (i < N_NODES) ? g_cnt[i] : 0;
    __syncthreads();
#pragma unroll
    for (int d = 1; d < 256; d <<= 1) {
        int v = (t >= d) ? s[t - d] : 0;
        __syncthreads();
        s[t] += v;
        __syncthreads();
    }
    if (i < N_NODES) g_off[i + 1] = s[t];      // partial inclusive
    if (t == 255) g_bsum[blockIdx.x] = s[255];
}

__global__ void k_scan_bsum() {
    __shared__ int s[512];
    int t = threadIdx.x;
    s[t] = (t < NBLK_SCAN) ? g_bsum[t] : 0;
    __syncthreads();
#pragma unroll
    for (int d = 1; d < 512; d <<= 1) {
        int v = (t >= d) ? s[t - d] : 0;
        __syncthreads();
        s[t] += v;
        __syncthreads();
    }
    if (t < NBLK_SCAN) g_bbase[t] = (t > 0) ? s[t - 1] : 0;  // exclusive
}

__global__ void k_scan_add() {
    int i = blockIdx.x * 256 + threadIdx.x;
    if (i < N_NODES) g_off[i + 1] += g_bbase[blockIdx.x];
    if (i == 0) g_off[0] = 0;
}

__global__ void k_fill(const int* __restrict__ src, const int* __restrict__ dst, int E) {
    int e = blockIdx.x * blockDim.x + threadIdx.x;
    if (e < E) {
        int d = dst[e];
        int pos = g_off[d] + atomicAdd(&g_cur[d], 1);
        g_csr[pos] = src[e];
    }
}

// ---------------------------------------------------------------
// GEMM1 with packed f32x2: g_h[row][c] = dinv[row]*sum_k x[row][k]*W1[k][c]
// BM=64, BN=128, BK=16, 128 threads, 8x8 per thread (4 row-pairs x 8 cols).
__global__ __launch_bounds__(128) void k_gemm1(const float* __restrict__ x,
                                               const float* __restrict__ W1) {
    __shared__ __align__(16) float As_t[16][64];   // [k][row] (transposed)
    __shared__ __align__(16) float Bs[16][128];
    const int tid  = threadIdx.x;
    const int row0 = blockIdx.x * 64;
    const int tcol = tid & 15;
    const int trow = tid >> 4;

    unsigned long long acc2[4][8];
#pragma unroll
    for (int p = 0; p < 4; p++)
#pragma unroll
        for (int j = 0; j < 8; j++) acc2[p][j] = 0ULL;

    for (int kt = 0; kt < D_IN / 16; kt++) {
        // A tile 64x16, stored transposed
#pragma unroll
        for (int t = tid; t < 256; t += 128) {
            int r = t >> 2, c = t & 3;
            int row = row0 + r;
            float4 v = make_float4(0.f, 0.f, 0.f, 0.f);
            if (row < N_NODES)
                v = *(const float4*)&x[(size_t)row * D_IN + kt * 16 + c * 4];
            As_t[c * 4 + 0][r] = v.x; As_t[c * 4 + 1][r] = v.y;
            As_t[c * 4 + 2][r] = v.z; As_t[c * 4 + 3][r] = v.w;
        }
        // B tile 16x128
#pragma unroll
        for (int t = tid; t < 512; t += 128) {
            int r = t >> 5, c = t & 31;
            *(float4*)&Bs[r][c * 4] = *(const float4*)&W1[(size_t)(kt * 16 + r) * D_HID + c * 4];
        }
        __syncthreads();
#pragma unroll
        for (int kk = 0; kk < 16; kk++) {
            ulonglong2 a01 = *(const ulonglong2*)&As_t[kk][trow * 8];
            ulonglong2 a23 = *(const ulonglong2*)&As_t[kk][trow * 8 + 4];
            unsigned long long av[4] = {a01.x, a01.y, a23.x, a23.y};
            float4 b0 = *(const float4*)&Bs[kk][tcol * 8];
            float4 b1 = *(const float4*)&Bs[kk][tcol * 8 + 4];
            unsigned long long bb[8];
            PK_DUP(bb[0], b0.x); PK_DUP(bb[1], b0.y);
            PK_DUP(bb[2], b0.z); PK_DUP(bb[3], b0.w);
            PK_DUP(bb[4], b1.x); PK_DUP(bb[5], b1.y);
            PK_DUP(bb[6], b1.z); PK_DUP(bb[7], b1.w);
#pragma unroll
            for (int p = 0; p < 4; p++)
#pragma unroll
                for (int j = 0; j < 8; j++) FMA_F32X2(acc2[p][j], av[p], bb[j]);
        }
        __syncthreads();
    }

#pragma unroll
    for (int p = 0; p < 4; p++) {
        int r0 = row0 + trow * 8 + 2 * p;      // rows r0, r0+1
        float lo[8], hi[8];
#pragma unroll
        for (int j = 0; j < 8; j++) {
            unsigned int ulo, uhi;
            UNPK(ulo, uhi, acc2[p][j]);
            lo[j] = __uint_as_float(ulo);
            hi[j] = __uint_as_float(uhi);
        }
        if (r0 < N_NODES) {
            float dv = g_dinv[r0];
            size_t base = (size_t)r0 * D_HID + tcol * 8;
            *(float4*)&g_h[base]     = make_float4(lo[0]*dv, lo[1]*dv, lo[2]*dv, lo[3]*dv);
            *(float4*)&g_h[base + 4] = make_float4(lo[4]*dv, lo[5]*dv, lo[6]*dv, lo[7]*dv);
        }
        if (r0 + 1 < N_NODES) {
            float dv = g_dinv[r0 + 1];
            size_t base = (size_t)(r0 + 1) * D_HID + tcol * 8;
            *(float4*)&g_h[base]     = make_float4(hi[0]*dv, hi[1]*dv, hi[2]*dv, hi[3]*dv);
            *(float4*)&g_h[base + 4] = make_float4(hi[4]*dv, hi[5]*dv, hi[6]*dv, hi[7]*dv);
        }
    }
}

// ---------------------------------------------------------------
// Layer-1 aggregation: block per node (128 threads = 128 cols)
// h1 = relu(dinv[n]*(g_h[n] + sum_{e in csr[n]} g_h[src]) + b1)
__global__ __launch_bounds__(128) void k_agg1(const float* __restrict__ b1) {
    int n = blockIdx.x;
    int c = threadIdx.x;
    float acc = g_h[(size_t)n * D_HID + c];    // self-loop
    int e0 = g_off[n], e1 = g_off[n + 1];
    for (int e = e0; e < e1; e++) {
        int s = g_csr[e];                       // broadcast load
        acc += g_h[(size_t)s * D_HID + c];
    }
    float v = fmaf(g_dinv[n], acc, b1[c]);
    g_h1[(size_t)n * D_HID + c] = fmaxf(v, 0.0f);
}

// ---------------------------------------------------------------
// GEMM2: g_h2[row][c] = dinv[row] * sum_k h1[row][k]*W2[k][c]  (c<47; pad=0)
// BM=64, BN=48, BK=32, 256 threads, 4x3 per thread.
__global__ __launch_bounds__(256) void k_gemm2(const float* __restrict__ W2) {
    __shared__ __align__(16) float As[64][32];
    __shared__ __align__(16) float Bs[D_HID][NC_PAD];
    const int tid  = threadIdx.x;
    const int row0 = blockIdx.x * 64;
    const int tcol = tid & 15;
    const int trow = tid >> 4;

    for (int t = tid; t < D_HID * NC_PAD; t += 256) {
        int r = t / NC_PAD, c = t % NC_PAD;
        Bs[r][c] = (c < N_CLS) ? W2[(size_t)r * N_CLS + c] : 0.0f;
    }
    __syncthreads();

    float acc[4][3];
#pragma unroll
    for (int i = 0; i < 4; i++)
#pragma unroll
        for (int j = 0; j < 3; j++) acc[i][j] = 0.0f;

    for (int kt = 0; kt < 4; kt++) {
#pragma unroll
        for (int t = tid; t < 512; t += 256) {
            int r = t >> 3, c = t & 7;
            int row = row0 + r;
            float4 v = make_float4(0.f, 0.f, 0.f, 0.f);
            if (row < N_NODES)
                v = *(const float4*)&g_h1[(size_t)row * D_HID + kt * 32 + c * 4];
            As[r][c * 4 + 0] = v.x; As[r][c * 4 + 1] = v.y;
            As[r][c * 4 + 2] = v.z; As[r][c * 4 + 3] = v.w;
        }
        __syncthreads();
#pragma unroll
        for (int kk = 0; kk < 32; kk++) {
            float a[4], b[3];
#pragma unroll
            for (int i = 0; i < 4; i++) a[i] = As[trow * 4 + i][kk];
#pragma unroll
            for (int j = 0; j < 3; j++) b[j] = Bs[kt * 32 + kk][tcol * 3 + j];
#pragma unroll
            for (int i = 0; i < 4; i++)
#pragma unroll
                for (int j = 0; j < 3; j++) acc[i][j] = fmaf(a[i], b[j], acc[i][j]);
        }
        __syncthreads();
    }

#pragma unroll
    for (int i = 0; i < 4; i++) {
        int row = row0 + trow * 4 + i;
        if (row < N_NODES) {
            float dv = g_dinv[row];
#pragma unroll
            for (int j = 0; j < 3; j++) {
                int col = tcol * 3 + j;
                g_h2[(size_t)row * NC_PAD + col] = (col < N_CLS) ? acc[i][j] * dv : 0.0f;
            }
        }
    }
}

// ---------------------------------------------------------------
// Layer-2 aggregation + final bias: 2 nodes per 96-thread block
__global__ __launch_bounds__(96) void k_agg2(const float* __restrict__ b2,
                                             float* __restrict__ out) {
    int sub = threadIdx.x / NC_PAD;            // 0 or 1
    int c   = threadIdx.x - sub * NC_PAD;      // 0..47
    int n   = blockIdx.x * 2 + sub;
    if (n >= N_NODES) return;
    float acc = g_h2[(size_t)n * NC_PAD + c];  // self-loop
    int e0 = g_off[n], e1 = g_off[n + 1];
    for (int e = e0; e < e1; e++) {
        int s = g_csr[e];
        acc += g_h2[(size_t)s * NC_PAD + c];
    }
    if (c < N_CLS)
        out[(size_t)n * N_CLS + c] = fmaf(g_dinv[n], acc, b2[c]);
}

// ---------------------------------------------------------------
extern "C" void kernel_launch(void* const* d_in, const int* in_sizes, int n_in,
                              void* d_out, int out_size) {
    const float* x    = (const float*)d_in[0];
    const int*   edge = (const int*)d_in[1];     // int32 (JAX x64 disabled)
    const float* W1   = (const float*)d_in[2];
    // b1 = d_in[3], W2 = d_in[4], b2 = d_in[5]
    const float* b1   = (const float*)d_in[3];
    const float* W2   = (const float*)d_in[4];
    const float* b2   = (const float*)d_in[5];
    float*       out  = (float*)d_out;

    const int E = in_sizes[1] / 2;
    const int* src = edge;
    const int* dst = edge + E;

    // CSR build
    k_init      <<<(N_NODES + 255) / 256, 256>>>();
    k_count     <<<(E + 255) / 256, 256>>>(dst, E);
    k_dinv      <<<(N_NODES + 255) / 256, 256>>>();
    k_scan_block<<<NBLK_SCAN, 256>>>();
    k_scan_bsum <<<1, 512>>>();
    k_scan_add  <<<NBLK_SCAN, 256>>>();
    k_fill      <<<(E + 255) / 256, 256>>>(src, dst, E);

    // Layer 1
    k_gemm1     <<<(N_NODES + 63) / 64, 128>>>(x, W1);
    k_agg1      <<<N_NODES, 128>>>(b1);

    // Layer 2
    k_gemm2     <<<(N_NODES + 63) / 64, 256>>>(W2);
    k_agg2      <<<(N_NODES + 1) / 2, 96>>>(b2, out);
}

// round 5
// speedup vs baseline: 3.0100x; 1.4308x over previous
#include <cuda_runtime.h>
#include <cuda_bf16.h>
#include <cstdint>

#define N_NODES 100000
#define N_EDGES 1600000
#define D_IN    256
#define D_HID   128
#define N_CLS   47
#define NC_PAD  48
#define NBLK_SCAN ((N_NODES + 255) / 256)   // 391
#define KP 72                                // padded smem row (bf16 elems)

// ---- scratch (static device globals) ----
__device__ __align__(16) float g_dinv[N_NODES];
__device__ int   g_cnt[N_NODES];
__device__ int   g_cur[N_NODES];
__device__ int   g_off[N_NODES + 1];
__device__ int   g_bsum[NBLK_SCAN];
__device__ int   g_bbase[NBLK_SCAN];
__device__ int   g_csr[N_EDGES];
__device__ __align__(16) float g_h [(size_t)N_NODES * D_HID];   // dinv[r]*(x@W1)
__device__ __align__(16) float g_h1[(size_t)N_NODES * D_HID];   // relu(gcn1)
__device__ __align__(16) float g_h2[(size_t)N_NODES * NC_PAD];  // dinv[r]*(h1@W2)
// W1 split into bf16 hi/lo, stored n-major [128][256]
__device__ __align__(16) __nv_bfloat16 g_W1bh[D_HID * D_IN];
__device__ __align__(16) __nv_bfloat16 g_W1bl[D_HID * D_IN];

// =====================  PTX helpers (baseline sm_80-class)  =====================
__device__ __forceinline__ uint32_t smem_u32(const void* p) {
    uint32_t a;
    asm("{ .reg .u64 t; cvta.to.shared.u64 t, %1; cvt.u32.u64 %0, t; }" : "=r"(a) : "l"(p));
    return a;
}
#define LDSM_X4(r, addr) \
    asm volatile("ldmatrix.sync.aligned.m8n8.x4.shared.b16 {%0,%1,%2,%3}, [%4];" \
        : "=r"((r)[0]), "=r"((r)[1]), "=r"((r)[2]), "=r"((r)[3]) : "r"(addr))

#define MMA16816(d, a, b) \
    asm volatile("mma.sync.aligned.m16n8k16.row.col.f32.bf16.bf16.f32 " \
        "{%0,%1,%2,%3}, {%4,%5,%6,%7}, {%8,%9}, {%0,%1,%2,%3};" \
        : "+f"((d)[0]), "+f"((d)[1]), "+f"((d)[2]), "+f"((d)[3]) \
        : "r"((a)[0]), "r"((a)[1]), "r"((a)[2]), "r"((a)[3]), "r"((b)[0]), "r"((b)[1]))

// =====================  CSR build  =====================
__global__ void k_init() {
    int i = blockIdx.x * blockDim.x + threadIdx.x;
    if (i < N_NODES) { g_cnt[i] = 0; g_cur[i] = 0; }
}
__global__ void k_count(const int* __restrict__ dst, int E) {
    int e = blockIdx.x * blockDim.x + threadIdx.x;
    if (e < E) atomicAdd(&g_cnt[dst[e]], 1);
}
__global__ void k_dinv() {
    int i = blockIdx.x * blockDim.x + threadIdx.x;
    if (i < N_NODES) g_dinv[i] = rsqrtf((float)g_cnt[i] + 1.0f);
}
__global__ void k_scan_block() {
    __shared__ int s[256];
    int i = blockIdx.x * 256 + threadIdx.x;
    int t = threadIdx.x;
    s[t] = (i < N_NODES) ? g_cnt[i] : 0;
    __syncthreads();
#pragma unroll
    for (int d = 1; d < 256; d <<= 1) {
        int v = (t >= d) ? s[t - d] : 0;
        __syncthreads();
        s[t] += v;
        __syncthreads();
    }
    if (i < N_NODES) g_off[i + 1] = s[t];
    if (t == 255) g_bsum[blockIdx.x] = s[255];
}
__global__ void k_scan_bsum() {
    __shared__ int s[512];
    int t = threadIdx.x;
    s[t] = (t < NBLK_SCAN) ? g_bsum[t] : 0;
    __syncthreads();
#pragma unroll
    for (int d = 1; d < 512; d <<= 1) {
        int v = (t >= d) ? s[t - d] : 0;
        __syncthreads();
        s[t] += v;
        __syncthreads();
    }
    if (t < NBLK_SCAN) g_bbase[t] = (t > 0) ? s[t - 1] : 0;
}
__global__ void k_scan_add() {
    int i = blockIdx.x * 256 + threadIdx.x;
    if (i < N_NODES) g_off[i + 1] += g_bbase[blockIdx.x];
    if (i == 0) g_off[0] = 0;
}
__global__ void k_fill(const int* __restrict__ src, const int* __restrict__ dst, int E) {
    int e = blockIdx.x * blockDim.x + threadIdx.x;
    if (e < E) {
        int d = dst[e];
        int pos = g_off[d] + atomicAdd(&g_cur[d], 1);
        g_csr[pos] = src[e];
    }
}

// =====================  W1 -> bf16 hi/lo images, n-major [n][k]  =====================
__global__ void k_splitW1(const float* __restrict__ W1) {
    int idx = blockIdx.x * blockDim.x + threadIdx.x;   // 32768
    if (idx >= D_HID * D_IN) return;
    int n = idx >> 8, k = idx & 255;
    float v = W1[(size_t)k * D_HID + n];
    __nv_bfloat16 h = __float2bfloat16_rz(v);          // truncation => lo exact-ish
    float lo = v - __bfloat162float(h);
    g_W1bh[n * D_IN + k] = h;
    g_W1bl[n * D_IN + k] = __float2bfloat16_rn(lo);
}

// =====================  GEMM1: bf16 3-pass mma.sync (fp32-accurate)  =====================
// D[128,128] = x[128,256] @ W1[256,128]; CTA 256 thr, 8 warps (4m x 2n), K-chunks of 64.
// smem: Ah[128][KP], Al, Bh[128][KP], Bl  (bf16)  = 4 * 18432 B = 73728 B
#define G1_SMEM (4 * 128 * KP * 2)

__global__ __launch_bounds__(256) void k_gemm1_mma(const float* __restrict__ x) {
    extern __shared__ char sm[];
    __nv_bfloat16* Ah = (__nv_bfloat16*)sm;
    __nv_bfloat16* Al = (__nv_bfloat16*)(sm + 18432);
    __nv_bfloat16* Bh = (__nv_bfloat16*)(sm + 36864);
    __nv_bfloat16* Bl = (__nv_bfloat16*)(sm + 55296);
    const uint32_t sAh = smem_u32(Ah), sAl = smem_u32(Al);
    const uint32_t sBh = smem_u32(Bh), sBl = smem_u32(Bl);

    const int tid  = threadIdx.x;
    const int wid  = tid >> 5;
    const int lane = tid & 31;
    const int row0 = blockIdx.x * 128;
    const int wm   = (wid & 3) * 32;    // warp m-origin (0..96)
    const int wn   = (wid >> 2) * 64;   // warp n-origin (0 or 64)

    float acc[2][8][4];
#pragma unroll
    for (int i = 0; i < 2; i++)
#pragma unroll
        for (int j = 0; j < 8; j++)
#pragma unroll
            for (int q = 0; q < 4; q++) acc[i][j][q] = 0.0f;

    for (int kc = 0; kc < 4; kc++) {
        // ---- A tile: load fp32, split hi/lo, store bf16 pairs ----
#pragma unroll
        for (int i = 0; i < 8; i++) {
            int idx = tid + i * 256;          // 0..2047
            int r = idx >> 4, c4 = idx & 15;  // row, float4-col
            int row = row0 + r;
            float4 v = make_float4(0.f, 0.f, 0.f, 0.f);
            if (row < N_NODES)
                v = *(const float4*)&x[(size_t)row * D_IN + kc * 64 + c4 * 4];
            uint32_t b0 = __float_as_uint(v.x), b1 = __float_as_uint(v.y);
            uint32_t b2 = __float_as_uint(v.z), b3 = __float_as_uint(v.w);
            uint32_t h01 = (b1 & 0xFFFF0000u) | (b0 >> 16);
            uint32_t h23 = (b3 & 0xFFFF0000u) | (b2 >> 16);
            float l0 = v.x - __uint_as_float(b0 & 0xFFFF0000u);
            float l1 = v.y - __uint_as_float(b1 & 0xFFFF0000u);
            float l2 = v.z - __uint_as_float(b2 & 0xFFFF0000u);
            float l3 = v.w - __uint_as_float(b3 & 0xFFFF0000u);
            __nv_bfloat162 p01 = __floats2bfloat162_rn(l0, l1);   // x=l0(lo half)
            __nv_bfloat162 p23 = __floats2bfloat162_rn(l2, l3);
            uint2 hh = make_uint2(h01, h23);
            uint2 ll = make_uint2(*(uint32_t*)&p01, *(uint32_t*)&p23);
            *(uint2*)(Ah + r * KP + c4 * 4) = hh;
            *(uint2*)(Al + r * KP + c4 * 4) = ll;
        }
        // ---- B tile: straight copy of pre-split images ----
#pragma unroll
        for (int i = 0; i < 8; i++) {
            int idx = tid + i * 256;          // 0..2047 uint2
            int n = idx >> 4, c = idx & 15;
            *(uint2*)(Bh + n * KP + c * 4) = *(const uint2*)&g_W1bh[n * D_IN + kc * 64 + c * 4];
            *(uint2*)(Bl + n * KP + c * 4) = *(const uint2*)&g_W1bl[n * D_IN + kc * 64 + c * 4];
        }
        __syncthreads();

        // ---- compute: 4 k16-steps ----
#pragma unroll
        for (int ks = 0; ks < 4; ks++) {
            int kB = ks * 16;
            int tl = lane >> 3, tr = lane & 7;

            uint32_t a_h[2][4], a_l[2][4];
#pragma unroll
            for (int mf = 0; mf < 2; mf++) {
                int rowA = wm + mf * 16 + (tl & 1) * 8 + tr;
                int colA = kB + (tl >> 1) * 8;
                uint32_t off = (uint32_t)(rowA * KP + colA) * 2;
                LDSM_X4(a_h[mf], sAh + off);
                LDSM_X4(a_l[mf], sAl + off);
            }
            uint32_t b_h[4][4], b_l[4][4];
#pragma unroll
            for (int nb = 0; nb < 4; nb++) {
                int rowB = wn + nb * 16 + (tl >> 1) * 8 + tr;
                int colB = kB + (tl & 1) * 8;
                uint32_t off = (uint32_t)(rowB * KP + colB) * 2;
                LDSM_X4(b_h[nb], sBh + off);
                LDSM_X4(b_l[nb], sBl + off);
            }
#pragma unroll
            for (int mf = 0; mf < 2; mf++)
#pragma unroll
                for (int nf = 0; nf < 8; nf++) {
                    uint32_t* bh = &b_h[nf >> 1][(nf & 1) * 2];
                    uint32_t* bl = &b_l[nf >> 1][(nf & 1) * 2];
                    MMA16816(acc[mf][nf], a_h[mf], bh);   // Ah*Bh
                    MMA16816(acc[mf][nf], a_h[mf], bl);   // Ah*Bl
                    MMA16816(acc[mf][nf], a_l[mf], bh);   // Al*Bh
                }
        }
        __syncthreads();
    }

    // ---- epilogue: scale by dinv, store ----
    int g  = lane >> 2;
    int tg = lane & 3;
#pragma unroll
    for (int mf = 0; mf < 2; mf++)
#pragma unroll
        for (int half = 0; half < 2; half++) {
            int row = row0 + wm + mf * 16 + half * 8 + g;
            if (row < N_NODES) {
                float dv = g_dinv[row];
#pragma unroll
                for (int nf = 0; nf < 8; nf++) {
                    int col = wn + nf * 8 + tg * 2;
                    float2 o;
                    o.x = acc[mf][nf][half * 2 + 0] * dv;
                    o.y = acc[mf][nf][half * 2 + 1] * dv;
                    *(float2*)&g_h[(size_t)row * D_HID + col] = o;
                }
            }
        }
}

// =====================  Layer-1 aggregation: warp per node  =====================
__global__ __launch_bounds__(128) void k_agg1(const float* __restrict__ b1) {
    int n = blockIdx.x * 4 + (threadIdx.x >> 5);
    int lane = threadIdx.x & 31;
    if (n >= N_NODES) return;
    const float4* hp = (const float4*)g_h;
    float4 acc = hp[(size_t)n * 32 + lane];     // self-loop
    int e0 = g_off[n], e1 = g_off[n + 1];
    for (int e = e0; e < e1; e++) {
        int s = g_csr[e];
        float4 v = hp[(size_t)s * 32 + lane];
        acc.x += v.x; acc.y += v.y; acc.z += v.z; acc.w += v.w;
    }
    float dv = g_dinv[n];
    float4 bb = ((const float4*)b1)[lane];
    float4 o;
    o.x = fmaxf(fmaf(dv, acc.x, bb.x), 0.f);
    o.y = fmaxf(fmaf(dv, acc.y, bb.y), 0.f);
    o.z = fmaxf(fmaf(dv, acc.z, bb.z), 0.f);
    o.w = fmaxf(fmaf(dv, acc.w, bb.w), 0.f);
    ((float4*)g_h1)[(size_t)n * 32 + lane] = o;
}

// =====================  GEMM2 (SIMT)  =====================
__global__ __launch_bounds__(256) void k_gemm2(const float* __restrict__ W2) {
    __shared__ __align__(16) float As[64][32];
    __shared__ __align__(16) float Bs[D_HID][NC_PAD];
    const int tid  = threadIdx.x;
    const int row0 = blockIdx.x * 64;
    const int tcol = tid & 15;
    const int trow = tid >> 4;

    for (int t = tid; t < D_HID * NC_PAD; t += 256) {
        int r = t / NC_PAD, c = t % NC_PAD;
        Bs[r][c] = (c < N_CLS) ? W2[(size_t)r * N_CLS + c] : 0.0f;
    }
    __syncthreads();

    float acc[4][3];
#pragma unroll
    for (int i = 0; i < 4; i++)
#pragma unroll
        for (int j = 0; j < 3; j++) acc[i][j] = 0.0f;

    for (int kt = 0; kt < 4; kt++) {
#pragma unroll
        for (int t = tid; t < 512; t += 256) {
            int r = t >> 3, c = t & 7;
            int row = row0 + r;
            float4 v = make_float4(0.f, 0.f, 0.f, 0.f);
            if (row < N_NODES)
                v = *(const float4*)&g_h1[(size_t)row * D_HID + kt * 32 + c * 4];
            As[r][c * 4 + 0] = v.x; As[r][c * 4 + 1] = v.y;
            As[r][c * 4 + 2] = v.z; As[r][c * 4 + 3] = v.w;
        }
        __syncthreads();
#pragma unroll
        for (int kk = 0; kk < 32; kk++) {
            float a[4], b[3];
#pragma unroll
            for (int i = 0; i < 4; i++) a[i] = As[trow * 4 + i][kk];
#pragma unroll
            for (int j = 0; j < 3; j++) b[j] = Bs[kt * 32 + kk][tcol * 3 + j];
#pragma unroll
            for (int i = 0; i < 4; i++)
#pragma unroll
                for (int j = 0; j < 3; j++) acc[i][j] = fmaf(a[i], b[j], acc[i][j]);
        }
        __syncthreads();
    }

#pragma unroll
    for (int i = 0; i < 4; i++) {
        int row = row0 + trow * 4 + i;
        if (row < N_NODES) {
            float dv = g_dinv[row];
#pragma unroll
            for (int j = 0; j < 3; j++) {
                int col = tcol * 3 + j;
                g_h2[(size_t)row * NC_PAD + col] = (col < N_CLS) ? acc[i][j] * dv : 0.0f;
            }
        }
    }
}

// =====================  Layer-2 aggregation + bias  =====================
__global__ __launch_bounds__(96) void k_agg2(const float* __restrict__ b2,
                                             float* __restrict__ out) {
    int sub = threadIdx.x / NC_PAD;
    int c   = threadIdx.x - sub * NC_PAD;
    int n   = blockIdx.x * 2 + sub;
    if (n >= N_NODES) return;
    float acc = g_h2[(size_t)n * NC_PAD + c];
    int e0 = g_off[n], e1 = g_off[n + 1];
    for (int e = e0; e < e1; e++) {
        int s = g_csr[e];
        acc += g_h2[(size_t)s * NC_PAD + c];
    }
    if (c < N_CLS)
        out[(size_t)n * N_CLS + c] = fmaf(g_dinv[n], acc, b2[c]);
}

// =====================  launch  =====================
extern "C" void kernel_launch(void* const* d_in, const int* in_sizes, int n_in,
                              void* d_out, int out_size) {
    const float* x    = (const float*)d_in[0];
    const int*   edge = (const int*)d_in[1];
    const float* W1   = (const float*)d_in[2];
    const float* b1   = (const float*)d_in[3];
    const float* W2   = (const float*)d_in[4];
    const float* b2   = (const float*)d_in[5];
    float*       out  = (float*)d_out;

    const int E = in_sizes[1] / 2;
    const int* src = edge;
    const int* dst = edge + E;

    cudaFuncSetAttribute(k_gemm1_mma, cudaFuncAttributeMaxDynamicSharedMemorySize, G1_SMEM);

    // CSR build
    k_init      <<<(N_NODES + 255) / 256, 256>>>();
    k_count     <<<(E + 255) / 256, 256>>>(dst, E);
    k_dinv      <<<(N_NODES + 255) / 256, 256>>>();
    k_scan_block<<<NBLK_SCAN, 256>>>();
    k_scan_bsum <<<1, 512>>>();
    k_scan_add  <<<NBLK_SCAN, 256>>>();
    k_fill      <<<(E + 255) / 256, 256>>>(src, dst, E);

    // Layer 1
    k_splitW1   <<<(D_HID * D_IN + 255) / 256, 256>>>(W1);
    k_gemm1_mma <<<(N_NODES + 127) / 128, 256, G1_SMEM>>>(x);
    k_agg1      <<<(N_NODES + 3) / 4, 128>>>(b1);

    // Layer 2
    k_gemm2     <<<(N_NODES + 63) / 64, 256>>>(W2);
    k_agg2      <<<(N_NODES + 1) / 2, 96>>>(b2, out);
}

// round 6
// speedup vs baseline: 3.5559x; 1.1814x over previous
#include <cuda_runtime.h>
#include <cuda_bf16.h>
#include <cuda_fp16.h>
#include <cstdint>

#define N_NODES 100000
#define N_EDGES 1600000
#define D_IN    256
#define D_HID   128
#define N_CLS   47
#define NC_PAD  48
#define NBLK_SCAN ((N_NODES + 255) / 256)   // 391
#define KP 72                                // padded smem row (bf16 elems)

// ---- scratch (static device globals) ----
__device__ __align__(16) float g_dinv[N_NODES];
__device__ int   g_cnt[N_NODES];
__device__ int   g_cur[N_NODES];
__device__ int   g_off[N_NODES + 1];
__device__ int   g_bsum[NBLK_SCAN];
__device__ int   g_bbase[NBLK_SCAN];
__device__ int   g_csr[N_EDGES];
__device__ __align__(16) __half g_hh [(size_t)N_NODES * D_HID];  // fp16: dinv*(x@W1)
__device__ __align__(16) float  g_h1 [(size_t)N_NODES * D_HID];  // fp32: relu(gcn1)
__device__ __align__(16) __half g_h2h[(size_t)N_NODES * NC_PAD]; // fp16: dinv*(h1@W2)
// weights split into bf16 hi/lo, n-major
__device__ __align__(16) __nv_bfloat16 g_W1bh[D_HID * D_IN];
__device__ __align__(16) __nv_bfloat16 g_W1bl[D_HID * D_IN];
__device__ __align__(16) __nv_bfloat16 g_W2bh[NC_PAD * D_HID];
__device__ __align__(16) __nv_bfloat16 g_W2bl[NC_PAD * D_HID];

// =====================  PTX helpers  =====================
__device__ __forceinline__ uint32_t smem_u32(const void* p) {
    uint32_t a;
    asm("{ .reg .u64 t; cvta.to.shared.u64 t, %1; cvt.u32.u64 %0, t; }" : "=r"(a) : "l"(p));
    return a;
}
#define LDSM_X4(r, addr) \
    asm volatile("ldmatrix.sync.aligned.m8n8.x4.shared.b16 {%0,%1,%2,%3}, [%4];" \
        : "=r"((r)[0]), "=r"((r)[1]), "=r"((r)[2]), "=r"((r)[3]) : "r"(addr))

#define MMA16816(d, a, b) \
    asm volatile("mma.sync.aligned.m16n8k16.row.col.f32.bf16.bf16.f32 " \
        "{%0,%1,%2,%3}, {%4,%5,%6,%7}, {%8,%9}, {%0,%1,%2,%3};" \
        : "+f"((d)[0]), "+f"((d)[1]), "+f"((d)[2]), "+f"((d)[3]) \
        : "r"((a)[0]), "r"((a)[1]), "r"((a)[2]), "r"((a)[3]), "r"((b)[0]), "r"((b)[1]))

// split one float4 into bf16-hi packed uint2 and bf16-lo packed uint2
__device__ __forceinline__ void split4(float4 v, uint2& hh, uint2& ll) {
    uint32_t b0 = __float_as_uint(v.x), b1 = __float_as_uint(v.y);
    uint32_t b2 = __float_as_uint(v.z), b3 = __float_as_uint(v.w);
    hh.x = (b1 & 0xFFFF0000u) | (b0 >> 16);
    hh.y = (b3 & 0xFFFF0000u) | (b2 >> 16);
    float l0 = v.x - __uint_as_float(b0 & 0xFFFF0000u);
    float l1 = v.y - __uint_as_float(b1 & 0xFFFF0000u);
    float l2 = v.z - __uint_as_float(b2 & 0xFFFF0000u);
    float l3 = v.w - __uint_as_float(b3 & 0xFFFF0000u);
    __nv_bfloat162 p01 = __floats2bfloat162_rn(l0, l1);
    __nv_bfloat162 p23 = __floats2bfloat162_rn(l2, l3);
    ll.x = *(uint32_t*)&p01;
    ll.y = *(uint32_t*)&p23;
}

// =====================  CSR build  =====================
__global__ void k_init() {
    int i = blockIdx.x * blockDim.x + threadIdx.x;
    if (i < N_NODES) { g_cnt[i] = 0; g_cur[i] = 0; }
}
__global__ void k_count(const int* __restrict__ dst, int E) {
    int e = blockIdx.x * blockDim.x + threadIdx.x;
    if (e < E) atomicAdd(&g_cnt[dst[e]], 1);
}
__global__ void k_dinv() {
    int i = blockIdx.x * blockDim.x + threadIdx.x;
    if (i < N_NODES) g_dinv[i] = rsqrtf((float)g_cnt[i] + 1.0f);
}
__global__ void k_scan_block() {
    __shared__ int s[256];
    int i = blockIdx.x * 256 + threadIdx.x;
    int t = threadIdx.x;
    s[t] = (i < N_NODES) ? g_cnt[i] : 0;
    __syncthreads();
#pragma unroll
    for (int d = 1; d < 256; d <<= 1) {
        int v = (t >= d) ? s[t - d] : 0;
        __syncthreads();
        s[t] += v;
        __syncthreads();
    }
    if (i < N_NODES) g_off[i + 1] = s[t];
    if (t == 255) g_bsum[blockIdx.x] = s[255];
}
__global__ void k_scan_bsum() {
    __shared__ int s[512];
    int t = threadIdx.x;
    s[t] = (t < NBLK_SCAN) ? g_bsum[t] : 0;
    __syncthreads();
#pragma unroll
    for (int d = 1; d < 512; d <<= 1) {
        int v = (t >= d) ? s[t - d] : 0;
        __syncthreads();
        s[t] += v;
        __syncthreads();
    }
    if (t < NBLK_SCAN) g_bbase[t] = (t > 0) ? s[t - 1] : 0;
}
__global__ void k_scan_add() {
    int i = blockIdx.x * 256 + threadIdx.x;
    if (i < N_NODES) g_off[i + 1] += g_bbase[blockIdx.x];
    if (i == 0) g_off[0] = 0;
}
__global__ void k_fill(const int* __restrict__ src, const int* __restrict__ dst, int E) {
    int e = blockIdx.x * blockDim.x + threadIdx.x;
    if (e < E) {
        int d = dst[e];
        int pos = g_off[d] + atomicAdd(&g_cur[d], 1);
        g_csr[pos] = src[e];
    }
}

// ===========  W1 & W2 -> bf16 hi/lo images, n-major  ===========
__global__ void k_splitW(const float* __restrict__ W1, const float* __restrict__ W2) {
    int idx = blockIdx.x * blockDim.x + threadIdx.x;
    if (idx < D_HID * D_IN) {
        int n = idx >> 8, k = idx & 255;
        float v = W1[(size_t)k * D_HID + n];
        __nv_bfloat16 h = __float2bfloat16_rz(v);
        float lo = v - __bfloat162float(h);
        g_W1bh[n * D_IN + k] = h;
        g_W1bl[n * D_IN + k] = __float2bfloat16_rn(lo);
    } else if (idx < D_HID * D_IN + NC_PAD * D_HID) {
        int j = idx - D_HID * D_IN;
        int n = j >> 7, k = j & 127;          // n: 0..47, k: 0..127
        float v = (n < N_CLS) ? W2[(size_t)k * N_CLS + n] : 0.0f;
        __nv_bfloat16 h = __float2bfloat16_rz(v);
        float lo = v - __bfloat162float(h);
        g_W2bh[n * D_HID + k] = h;
        g_W2bl[n * D_HID + k] = __float2bfloat16_rn(lo);
    }
}

// =====================  GEMM1: bf16 3-pass mma.sync  =====================
// D[128,128] = x[128,256] @ W1[256,128]; 256 thr, 8 warps (4m x 2n), K-chunks 64.
#define G1_SMEM (4 * 128 * KP * 2)

__global__ __launch_bounds__(256) void k_gemm1_mma(const float* __restrict__ x) {
    extern __shared__ char sm[];
    __nv_bfloat16* Ah = (__nv_bfloat16*)sm;
    __nv_bfloat16* Al = (__nv_bfloat16*)(sm + 18432);
    __nv_bfloat16* Bh = (__nv_bfloat16*)(sm + 36864);
    __nv_bfloat16* Bl = (__nv_bfloat16*)(sm + 55296);
    const uint32_t sAh = smem_u32(Ah), sAl = smem_u32(Al);
    const uint32_t sBh = smem_u32(Bh), sBl = smem_u32(Bl);

    const int tid  = threadIdx.x;
    const int wid  = tid >> 5;
    const int lane = tid & 31;
    const int row0 = blockIdx.x * 128;
    const int wm   = (wid & 3) * 32;
    const int wn   = (wid >> 2) * 64;

    float acc[2][8][4];
#pragma unroll
    for (int i = 0; i < 2; i++)
#pragma unroll
        for (int j = 0; j < 8; j++)
#pragma unroll
            for (int q = 0; q < 4; q++) acc[i][j][q] = 0.0f;

    for (int kc = 0; kc < 4; kc++) {
#pragma unroll
        for (int i = 0; i < 8; i++) {
            int idx = tid + i * 256;
            int r = idx >> 4, c4 = idx & 15;
            int row = row0 + r;
            float4 v = make_float4(0.f, 0.f, 0.f, 0.f);
            if (row < N_NODES)
                v = *(const float4*)&x[(size_t)row * D_IN + kc * 64 + c4 * 4];
            uint2 hh, ll;
            split4(v, hh, ll);
            *(uint2*)(Ah + r * KP + c4 * 4) = hh;
            *(uint2*)(Al + r * KP + c4 * 4) = ll;
        }
#pragma unroll
        for (int i = 0; i < 8; i++) {
            int idx = tid + i * 256;
            int n = idx >> 4, c = idx & 15;
            *(uint2*)(Bh + n * KP + c * 4) = *(const uint2*)&g_W1bh[n * D_IN + kc * 64 + c * 4];
            *(uint2*)(Bl + n * KP + c * 4) = *(const uint2*)&g_W1bl[n * D_IN + kc * 64 + c * 4];
        }
        __syncthreads();

#pragma unroll
        for (int ks = 0; ks < 4; ks++) {
            int kB = ks * 16;
            int tl = lane >> 3, tr = lane & 7;

            uint32_t a_h[2][4], a_l[2][4];
#pragma unroll
            for (int mf = 0; mf < 2; mf++) {
                int rowA = wm + mf * 16 + (tl & 1) * 8 + tr;
                int colA = kB + (tl >> 1) * 8;
                uint32_t off = (uint32_t)(rowA * KP + colA) * 2;
                LDSM_X4(a_h[mf], sAh + off);
                LDSM_X4(a_l[mf], sAl + off);
            }
            uint32_t b_h[4][4], b_l[4][4];
#pragma unroll
            for (int nb = 0; nb < 4; nb++) {
                int rowB = wn + nb * 16 + (tl >> 1) * 8 + tr;
                int colB = kB + (tl & 1) * 8;
                uint32_t off = (uint32_t)(rowB * KP + colB) * 2;
                LDSM_X4(b_h[nb], sBh + off);
                LDSM_X4(b_l[nb], sBl + off);
            }
#pragma unroll
            for (int mf = 0; mf < 2; mf++)
#pragma unroll
                for (int nf = 0; nf < 8; nf++) {
                    uint32_t* bh = &b_h[nf >> 1][(nf & 1) * 2];
                    uint32_t* bl = &b_l[nf >> 1][(nf & 1) * 2];
                    MMA16816(acc[mf][nf], a_h[mf], bh);
                    MMA16816(acc[mf][nf], a_h[mf], bl);
                    MMA16816(acc[mf][nf], a_l[mf], bh);
                }
        }
        __syncthreads();
    }

    // epilogue: scale by dinv, store fp16
    int g  = lane >> 2;
    int tg = lane & 3;
#pragma unroll
    for (int mf = 0; mf < 2; mf++)
#pragma unroll
        for (int half = 0; half < 2; half++) {
            int row = row0 + wm + mf * 16 + half * 8 + g;
            if (row < N_NODES) {
                float dv = g_dinv[row];
#pragma unroll
                for (int nf = 0; nf < 8; nf++) {
                    int col = wn + nf * 8 + tg * 2;
                    __half2 o = __floats2half2_rn(acc[mf][nf][half * 2 + 0] * dv,
                                                  acc[mf][nf][half * 2 + 1] * dv);
                    *(__half2*)&g_hh[(size_t)row * D_HID + col] = o;
                }
            }
        }
}

// =====================  Layer-1 aggregation: warp per node (fp16 gather)  =====================
__global__ __launch_bounds__(128) void k_agg1(const float* __restrict__ b1) {
    int n = blockIdx.x * 4 + (threadIdx.x >> 5);
    int lane = threadIdx.x & 31;
    if (n >= N_NODES) return;
    const uint2* hp = (const uint2*)g_hh;          // 4 halves per uint2, 32 per row
    uint2 sv = hp[(size_t)n * 32 + lane];          // self-loop
    __half2* ph = (__half2*)&sv;
    float2 a0 = __half22float2(ph[0]);
    float2 a1 = __half22float2(ph[1]);
    int e0 = g_off[n], e1 = g_off[n + 1];
    for (int e = e0; e < e1; e++) {
        int s = g_csr[e];                           // broadcast
        uint2 v = hp[(size_t)s * 32 + lane];
        __half2* pv = (__half2*)&v;
        float2 f0 = __half22float2(pv[0]);
        float2 f1 = __half22float2(pv[1]);
        a0.x += f0.x; a0.y += f0.y; a1.x += f1.x; a1.y += f1.y;
    }
    float dv = g_dinv[n];
    float4 bb = ((const float4*)b1)[lane];
    float4 o;
    o.x = fmaxf(fmaf(dv, a0.x, bb.x), 0.f);
    o.y = fmaxf(fmaf(dv, a0.y, bb.y), 0.f);
    o.z = fmaxf(fmaf(dv, a1.x, bb.z), 0.f);
    o.w = fmaxf(fmaf(dv, a1.y, bb.w), 0.f);
    ((float4*)g_h1)[(size_t)n * 32 + lane] = o;
}

// =====================  GEMM2: bf16 3-pass mma.sync (M=128, N=48, K=128)  =====================
// 128 threads, 4 warps; warp w: rows w*32..+31 (2 m16 frags), all 48 cols (6 n8 frags).
#define G2_A   (128 * KP * 2)                       // 18432
#define G2_B   (NC_PAD * KP * 2)                    // 6912
#define G2_SMEM (2 * G2_A + 2 * G2_B)               // 50688

__global__ __launch_bounds__(128) void k_gemm2_mma() {
    extern __shared__ char sm[];
    __nv_bfloat16* Ah = (__nv_bfloat16*)sm;
    __nv_bfloat16* Al = (__nv_bfloat16*)(sm + G2_A);
    __nv_bfloat16* Bh = (__nv_bfloat16*)(sm + 2 * G2_A);
    __nv_bfloat16* Bl = (__nv_bfloat16*)(sm + 2 * G2_A + G2_B);
    const uint32_t sAh = smem_u32(Ah), sAl = smem_u32(Al);
    const uint32_t sBh = smem_u32(Bh), sBl = smem_u32(Bl);

    const int tid  = threadIdx.x;
    const int wid  = tid >> 5;
    const int lane = tid & 31;
    const int row0 = blockIdx.x * 128;
    const int wm   = wid * 32;

    float acc[2][6][4];
#pragma unroll
    for (int i = 0; i < 2; i++)
#pragma unroll
        for (int j = 0; j < 6; j++)
#pragma unroll
            for (int q = 0; q < 4; q++) acc[i][j][q] = 0.0f;

    for (int kc = 0; kc < 2; kc++) {
        // A tile: 128x64 fp32 -> split
#pragma unroll
        for (int i = 0; i < 16; i++) {
            int idx = tid + i * 128;
            int r = idx >> 4, c4 = idx & 15;
            int row = row0 + r;
            float4 v = make_float4(0.f, 0.f, 0.f, 0.f);
            if (row < N_NODES)
                v = *(const float4*)&g_h1[(size_t)row * D_HID + kc * 64 + c4 * 4];
            uint2 hh, ll;
            split4(v, hh, ll);
            *(uint2*)(Ah + r * KP + c4 * 4) = hh;
            *(uint2*)(Al + r * KP + c4 * 4) = ll;
        }
        // B tile: 48x64 straight copy
#pragma unroll
        for (int i = 0; i < 6; i++) {
            int idx = tid + i * 128;
            int n = idx >> 4, c = idx & 15;
            *(uint2*)(Bh + n * KP + c * 4) = *(const uint2*)&g_W2bh[n * D_HID + kc * 64 + c * 4];
            *(uint2*)(Bl + n * KP + c * 4) = *(const uint2*)&g_W2bl[n * D_HID + kc * 64 + c * 4];
        }
        __syncthreads();

#pragma unroll
        for (int ks = 0; ks < 4; ks++) {
            int kB = ks * 16;
            int tl = lane >> 3, tr = lane & 7;

            uint32_t a_h[2][4], a_l[2][4];
#pragma unroll
            for (int mf = 0; mf < 2; mf++) {
                int rowA = wm + mf * 16 + (tl & 1) * 8 + tr;
                int colA = kB + (tl >> 1) * 8;
                uint32_t off = (uint32_t)(rowA * KP + colA) * 2;
                LDSM_X4(a_h[mf], sAh + off);
                LDSM_X4(a_l[mf], sAl + off);
            }
            uint32_t b_h[3][4], b_l[3][4];
#pragma unroll
            for (int nb = 0; nb < 3; nb++) {
                int rowB = nb * 16 + (tl >> 1) * 8 + tr;
                int colB = kB + (tl & 1) * 8;
                uint32_t off = (uint32_t)(rowB * KP + colB) * 2;
                LDSM_X4(b_h[nb], sBh + off);
                LDSM_X4(b_l[nb], sBl + off);
            }
#pragma unroll
            for (int mf = 0; mf < 2; mf++)
#pragma unroll
                for (int nf = 0; nf < 6; nf++) {
                    uint32_t* bh = &b_h[nf >> 1][(nf & 1) * 2];
                    uint32_t* bl = &b_l[nf >> 1][(nf & 1) * 2];
                    MMA16816(acc[mf][nf], a_h[mf], bh);
                    MMA16816(acc[mf][nf], a_h[mf], bl);
                    MMA16816(acc[mf][nf], a_l[mf], bh);
                }
        }
        __syncthreads();
    }

    // epilogue: scale by dinv, store fp16 (padded 48)
    int g  = lane >> 2;
    int tg = lane & 3;
#pragma unroll
    for (int mf = 0; mf < 2; mf++)
#pragma unroll
        for (int half = 0; half < 2; half++) {
            int row = row0 + wm + mf * 16 + half * 8 + g;
            if (row < N_NODES) {
                float dv = g_dinv[row];
#pragma unroll
                for (int nf = 0; nf < 6; nf++) {
                    int col = nf * 8 + tg * 2;
                    __half2 o = __floats2half2_rn(acc[mf][nf][half * 2 + 0] * dv,
                                                  acc[mf][nf][half * 2 + 1] * dv);
                    *(__half2*)&g_h2h[(size_t)row * NC_PAD + col] = o;
                }
            }
        }
}

// =====================  Layer-2 aggregation + bias (fp16 gather)  =====================
__global__ __launch_bounds__(128) void k_agg2(const float* __restrict__ b2,
                                              float* __restrict__ out) {
    int n = blockIdx.x * 4 + (threadIdx.x >> 5);
    int lane = threadIdx.x & 31;
    if (n >= N_NODES) return;
    const uint2* hp = (const uint2*)g_h2h;          // 12 uint2 per row (48 halves)
    int e0 = g_off[n], e1 = g_off[n + 1];
    float2 a0 = make_float2(0.f, 0.f), a1 = make_float2(0.f, 0.f);
    if (lane < 12) {
        uint2 sv = hp[(size_t)n * 12 + lane];
        __half2* ph = (__half2*)&sv;
        a0 = __half22float2(ph[0]);
        a1 = __half22float2(ph[1]);
    }
    for (int e = e0; e < e1; e++) {
        int s = g_csr[e];
        if (lane < 12) {
            uint2 v = hp[(size_t)s * 12 + lane];
            __half2* pv = (__half2*)&v;
            float2 f0 = __half22float2(pv[0]);
            float2 f1 = __half22float2(pv[1]);
            a0.x += f0.x; a0.y += f0.y; a1.x += f1.x; a1.y += f1.y;
        }
    }
    if (lane < 12) {
        float dv = g_dinv[n];
        int c = lane * 4;
        float r[4] = {a0.x, a0.y, a1.x, a1.y};
#pragma unroll
        for (int j = 0; j < 4; j++) {
            int col = c + j;
            if (col < N_CLS)
                out[(size_t)n * N_CLS + col] = fmaf(dv, r[j], b2[col]);
        }
    }
}

// =====================  launch  =====================
extern "C" void kernel_launch(void* const* d_in, const int* in_sizes, int n_in,
                              void* d_out, int out_size) {
    const float* x    = (const float*)d_in[0];
    const int*   edge = (const int*)d_in[1];
    const float* W1   = (const float*)d_in[2];
    const float* b1   = (const float*)d_in[3];
    const float* W2   = (const float*)d_in[4];
    const float* b2   = (const float*)d_in[5];
    float*       out  = (float*)d_out;

    const int E = in_sizes[1] / 2;
    const int* src = edge;
    const int* dst = edge + E;

    cudaFuncSetAttribute(k_gemm1_mma, cudaFuncAttributeMaxDynamicSharedMemorySize, G1_SMEM);
    cudaFuncSetAttribute(k_gemm2_mma, cudaFuncAttributeMaxDynamicSharedMemorySize, G2_SMEM);

    // CSR build
    k_init      <<<(N_NODES + 255) / 256, 256>>>();
    k_count     <<<(E + 255) / 256, 256>>>(dst, E);
    k_dinv      <<<(N_NODES + 255) / 256, 256>>>();
    k_scan_block<<<NBLK_SCAN, 256>>>();
    k_scan_bsum <<<1, 512>>>();
    k_scan_add  <<<NBLK_SCAN, 256>>>();
    k_fill      <<<(E + 255) / 256, 256>>>(src, dst, E);

    // weight prep
    int wtot = D_HID * D_IN + NC_PAD * D_HID;
    k_splitW    <<<(wtot + 255) / 256, 256>>>(W1, W2);

    // Layer 1
    k_gemm1_mma <<<(N_NODES + 127) / 128, 256, G1_SMEM>>>(x);
    k_agg1      <<<(N_NODES + 3) / 4, 128>>>(b1);

    // Layer 2
    k_gemm2_mma <<<(N_NODES + 127) / 128, 128, G2_SMEM>>>();
    k_agg2      <<<(N_NODES + 3) / 4, 128>>>(b2, out);
}

// round 7
// speedup vs baseline: 4.6456x; 1.3065x over previous
#include <cuda_runtime.h>
#include <cuda_fp16.h>
#include <cstdint>

#define N_NODES 100000
#define N_EDGES 1600000
#define D_IN    256
#define D_HID   128
#define N_CLS   47
#define NC_PAD  48
#define NBLK_SCAN ((N_NODES + 255) / 256)   // 391
#define KP  72                               // gemm1 smem row (halves)
#define KP2 136                              // gemm2 smem row (halves)

// ---- scratch (static device globals) ----
__device__ __align__(16) float g_dinv[N_NODES];
__device__ int   g_cnt[N_NODES];
__device__ int   g_cur[N_NODES];
__device__ int   g_off[N_NODES + 1];
__device__ int   g_bsum[NBLK_SCAN];
__device__ int   g_bbase[NBLK_SCAN];
__device__ int   g_csr[N_EDGES];
__device__ __align__(16) __half g_hh [(size_t)N_NODES * D_HID];  // dinv*(x@W1)
__device__ __align__(16) __half g_h1h[(size_t)N_NODES * D_HID];  // relu(gcn1)
__device__ __align__(16) __half g_h2h[(size_t)N_NODES * NC_PAD]; // dinv*(h1@W2)
// fp16 weights, n-major
__device__ __align__(16) __half g_W1f[D_HID * D_IN];
__device__ __align__(16) __half g_W2f[NC_PAD * D_HID];

// =====================  PTX helpers  =====================
__device__ __forceinline__ uint32_t smem_u32(const void* p) {
    uint32_t a;
    asm("{ .reg .u64 t; cvta.to.shared.u64 t, %1; cvt.u32.u64 %0, t; }" : "=r"(a) : "l"(p));
    return a;
}
#define LDSM_X4(r, addr) \
    asm volatile("ldmatrix.sync.aligned.m8n8.x4.shared.b16 {%0,%1,%2,%3}, [%4];" \
        : "=r"((r)[0]), "=r"((r)[1]), "=r"((r)[2]), "=r"((r)[3]) : "r"(addr))

#define MMA16816H(d, a, b) \
    asm volatile("mma.sync.aligned.m16n8k16.row.col.f32.f16.f16.f32 " \
        "{%0,%1,%2,%3}, {%4,%5,%6,%7}, {%8,%9}, {%0,%1,%2,%3};" \
        : "+f"((d)[0]), "+f"((d)[1]), "+f"((d)[2]), "+f"((d)[3]) \
        : "r"((a)[0]), "r"((a)[1]), "r"((a)[2]), "r"((a)[3]), "r"((b)[0]), "r"((b)[1]))

// =====================  CSR build  =====================
__global__ void k_init() {
    int i = blockIdx.x * blockDim.x + threadIdx.x;
    if (i < N_NODES) { g_cnt[i] = 0; g_cur[i] = 0; }
}
__global__ void k_count(const int* __restrict__ dst, int E) {
    int e = blockIdx.x * blockDim.x + threadIdx.x;
    if (e < E) atomicAdd(&g_cnt[dst[e]], 1);
}
__global__ void k_scan_block() {      // also computes dinv
    __shared__ int s[256];
    int i = blockIdx.x * 256 + threadIdx.x;
    int t = threadIdx.x;
    int cnt = (i < N_NODES) ? g_cnt[i] : 0;
    if (i < N_NODES) g_dinv[i] = rsqrtf((float)cnt + 1.0f);
    s[t] = cnt;
    __syncthreads();
#pragma unroll
    for (int d = 1; d < 256; d <<= 1) {
        int v = (t >= d) ? s[t - d] : 0;
        __syncthreads();
        s[t] += v;
        __syncthreads();
    }
    if (i < N_NODES) g_off[i + 1] = s[t];
    if (t == 255) g_bsum[blockIdx.x] = s[255];
}
__global__ void k_scan_bsum() {
    __shared__ int s[512];
    int t = threadIdx.x;
    s[t] = (t < NBLK_SCAN) ? g_bsum[t] : 0;
    __syncthreads();
#pragma unroll
    for (int d = 1; d < 512; d <<= 1) {
        int v = (t >= d) ? s[t - d] : 0;
        __syncthreads();
        s[t] += v;
        __syncthreads();
    }
    if (t < NBLK_SCAN) g_bbase[t] = (t > 0) ? s[t - 1] : 0;
}
__global__ void k_scan_add() {
    int i = blockIdx.x * 256 + threadIdx.x;
    if (i < N_NODES) g_off[i + 1] += g_bbase[blockIdx.x];
    if (i == 0) g_off[0] = 0;
}
__global__ void k_fill(const int* __restrict__ src, const int* __restrict__ dst, int E) {
    int e = blockIdx.x * blockDim.x + threadIdx.x;
    if (e < E) {
        int d = dst[e];
        int pos = g_off[d] + atomicAdd(&g_cur[d], 1);
        g_csr[pos] = src[e];
    }
}

// ===========  weights -> fp16, n-major  ===========
__global__ void k_cvtW(const float* __restrict__ W1, const float* __restrict__ W2) {
    int idx = blockIdx.x * blockDim.x + threadIdx.x;
    if (idx < D_HID * D_IN) {
        int n = idx >> 8, k = idx & 255;
        g_W1f[n * D_IN + k] = __float2half_rn(W1[(size_t)k * D_HID + n]);
    } else if (idx < D_HID * D_IN + NC_PAD * D_HID) {
        int j = idx - D_HID * D_IN;
        int n = j >> 7, k = j & 127;
        float v = (n < N_CLS) ? W2[(size_t)k * N_CLS + n] : 0.0f;
        g_W2f[n * D_HID + k] = __float2half_rn(v);
    }
}

// =====================  GEMM1: single-pass fp16 mma  =====================
// D[128,128] = x[128,256] @ W1[256,128]; 256 thr, 8 warps (4m x 2n), K-chunks 64.
__global__ __launch_bounds__(256) void k_gemm1_mma(const float* __restrict__ x) {
    __shared__ __align__(16) __half As[128 * KP];   // 18432 B
    __shared__ __align__(16) __half Bs[128 * KP];   // 18432 B
    const uint32_t sA = smem_u32(As), sB = smem_u32(Bs);

    const int tid  = threadIdx.x;
    const int wid  = tid >> 5;
    const int lane = tid & 31;
    const int row0 = blockIdx.x * 128;
    const int wm   = (wid & 3) * 32;
    const int wn   = (wid >> 2) * 64;

    float acc[2][8][4];
#pragma unroll
    for (int i = 0; i < 2; i++)
#pragma unroll
        for (int j = 0; j < 8; j++)
#pragma unroll
            for (int q = 0; q < 4; q++) acc[i][j][q] = 0.0f;

    for (int kc = 0; kc < 4; kc++) {
        // A: 128 rows x 64 floats -> fp16
#pragma unroll
        for (int i = 0; i < 8; i++) {
            int idx = tid + i * 256;
            int r = idx >> 4, c4 = idx & 15;
            int row = row0 + r;
            float4 v = make_float4(0.f, 0.f, 0.f, 0.f);
            if (row < N_NODES)
                v = *(const float4*)&x[(size_t)row * D_IN + kc * 64 + c4 * 4];
            __half2 h01 = __floats2half2_rn(v.x, v.y);
            __half2 h23 = __floats2half2_rn(v.z, v.w);
            uint2 u = make_uint2(*(uint32_t*)&h01, *(uint32_t*)&h23);
            *(uint2*)(As + r * KP + c4 * 4) = u;
        }
        // B: straight copy of fp16 image
#pragma unroll
        for (int i = 0; i < 8; i++) {
            int idx = tid + i * 256;
            int n = idx >> 4, c = idx & 15;
            *(uint2*)(Bs + n * KP + c * 4) = *(const uint2*)&g_W1f[n * D_IN + kc * 64 + c * 4];
        }
        __syncthreads();

#pragma unroll
        for (int ks = 0; ks < 4; ks++) {
            int kB = ks * 16;
            int tl = lane >> 3, tr = lane & 7;

            uint32_t a[2][4];
#pragma unroll
            for (int mf = 0; mf < 2; mf++) {
                int rowA = wm + mf * 16 + (tl & 1) * 8 + tr;
                int colA = kB + (tl >> 1) * 8;
                LDSM_X4(a[mf], sA + (uint32_t)(rowA * KP + colA) * 2);
            }
            uint32_t b[4][4];
#pragma unroll
            for (int nb = 0; nb < 4; nb++) {
                int rowB = wn + nb * 16 + (tl >> 1) * 8 + tr;
                int colB = kB + (tl & 1) * 8;
                LDSM_X4(b[nb], sB + (uint32_t)(rowB * KP + colB) * 2);
            }
#pragma unroll
            for (int mf = 0; mf < 2; mf++)
#pragma unroll
                for (int nf = 0; nf < 8; nf++)
                    MMA16816H(acc[mf][nf], a[mf], (&b[nf >> 1][(nf & 1) * 2]));
        }
        __syncthreads();
    }

    // epilogue: scale by dinv, store fp16
    int g  = lane >> 2;
    int tg = lane & 3;
#pragma unroll
    for (int mf = 0; mf < 2; mf++)
#pragma unroll
        for (int half = 0; half < 2; half++) {
            int row = row0 + wm + mf * 16 + half * 8 + g;
            if (row < N_NODES) {
                float dv = g_dinv[row];
#pragma unroll
                for (int nf = 0; nf < 8; nf++) {
                    int col = wn + nf * 8 + tg * 2;
                    __half2 o = __floats2half2_rn(acc[mf][nf][half * 2 + 0] * dv,
                                                  acc[mf][nf][half * 2 + 1] * dv);
                    *(__half2*)&g_hh[(size_t)row * D_HID + col] = o;
                }
            }
        }
}

// =====================  Layer-1 aggregation: warp per node  =====================
__global__ __launch_bounds__(128) void k_agg1(const float* __restrict__ b1) {
    int n = blockIdx.x * 4 + (threadIdx.x >> 5);
    int lane = threadIdx.x & 31;
    if (n >= N_NODES) return;
    const uint2* hp = (const uint2*)g_hh;           // 32 uint2 per row
    uint2 sv = hp[(size_t)n * 32 + lane];           // self-loop
    __half2* ph = (__half2*)&sv;
    float2 a0 = __half22float2(ph[0]);
    float2 a1 = __half22float2(ph[1]);
    int e0 = g_off[n], e1 = g_off[n + 1];
    for (int e = e0; e < e1; e++) {
        int s = g_csr[e];                            // broadcast
        uint2 v = hp[(size_t)s * 32 + lane];
        __half2* pv = (__half2*)&v;
        float2 f0 = __half22float2(pv[0]);
        float2 f1 = __half22float2(pv[1]);
        a0.x += f0.x; a0.y += f0.y; a1.x += f1.x; a1.y += f1.y;
    }
    float dv = g_dinv[n];
    float4 bb = ((const float4*)b1)[lane];
    __half2 o01 = __floats2half2_rn(fmaxf(fmaf(dv, a0.x, bb.x), 0.f),
                                    fmaxf(fmaf(dv, a0.y, bb.y), 0.f));
    __half2 o23 = __floats2half2_rn(fmaxf(fmaf(dv, a1.x, bb.z), 0.f),
                                    fmaxf(fmaf(dv, a1.y, bb.w), 0.f));
    uint2 u = make_uint2(*(uint32_t*)&o01, *(uint32_t*)&o23);
    ((uint2*)g_h1h)[(size_t)n * 32 + lane] = u;
}

// =====================  GEMM2: single-pass fp16 (M=128, N=48, K=128)  =====================
__global__ __launch_bounds__(128) void k_gemm2_mma() {
    __shared__ __align__(16) __half As[128 * KP2];  // 34816 B
    __shared__ __align__(16) __half Bs[NC_PAD * KP2]; // 13056 B
    const uint32_t sA = smem_u32(As), sB = smem_u32(Bs);

    const int tid  = threadIdx.x;
    const int wid  = tid >> 5;
    const int lane = tid & 31;
    const int row0 = blockIdx.x * 128;
    const int wm   = wid * 32;

    // A: 128 rows x 128 halves = 2048 uint4
#pragma unroll
    for (int i = 0; i < 16; i++) {
        int idx = tid + i * 128;
        int r = idx >> 4, c = idx & 15;          // 16 uint4 per row
        int row = row0 + r;
        uint4 u = make_uint4(0u, 0u, 0u, 0u);
        if (row < N_NODES)
            u = *(const uint4*)&g_h1h[(size_t)row * D_HID + c * 8];
        *(uint4*)(As + r * KP2 + c * 8) = u;
    }
    // B: 48 rows x 128 halves = 768 uint4
#pragma unroll
    for (int i = 0; i < 6; i++) {
        int idx = tid + i * 128;
        int n = idx >> 4, c = idx & 15;
        *(uint4*)(Bs + n * KP2 + c * 8) = *(const uint4*)&g_W2f[n * D_HID + c * 8];
    }
    __syncthreads();

    float acc[2][6][4];
#pragma unroll
    for (int i = 0; i < 2; i++)
#pragma unroll
        for (int j = 0; j < 6; j++)
#pragma unroll
            for (int q = 0; q < 4; q++) acc[i][j][q] = 0.0f;

#pragma unroll
    for (int ks = 0; ks < 8; ks++) {
        int kB = ks * 16;
        int tl = lane >> 3, tr = lane & 7;

        uint32_t a[2][4];
#pragma unroll
        for (int mf = 0; mf < 2; mf++) {
            int rowA = wm + mf * 16 + (tl & 1) * 8 + tr;
            int colA = kB + (tl >> 1) * 8;
            LDSM_X4(a[mf], sA + (uint32_t)(rowA * KP2 + colA) * 2);
        }
        uint32_t b[3][4];
#pragma unroll
        for (int nb = 0; nb < 3; nb++) {
            int rowB = nb * 16 + (tl >> 1) * 8 + tr;
            int colB = kB + (tl & 1) * 8;
            LDSM_X4(b[nb], sB + (uint32_t)(rowB * KP2 + colB) * 2);
        }
#pragma unroll
        for (int mf = 0; mf < 2; mf++)
#pragma unroll
            for (int nf = 0; nf < 6; nf++)
                MMA16816H(acc[mf][nf], a[mf], (&b[nf >> 1][(nf & 1) * 2]));
    }

    // epilogue
    int g  = lane >> 2;
    int tg = lane & 3;
#pragma unroll
    for (int mf = 0; mf < 2; mf++)
#pragma unroll
        for (int half = 0; half < 2; half++) {
            int row = row0 + wm + mf * 16 + half * 8 + g;
            if (row < N_NODES) {
                float dv = g_dinv[row];
#pragma unroll
                for (int nf = 0; nf < 6; nf++) {
                    int col = nf * 8 + tg * 2;
                    __half2 o = __floats2half2_rn(acc[mf][nf][half * 2 + 0] * dv,
                                                  acc[mf][nf][half * 2 + 1] * dv);
                    *(__half2*)&g_h2h[(size_t)row * NC_PAD + col] = o;
                }
            }
        }
}

// =====================  Layer-2 aggregation + bias  =====================
__global__ __launch_bounds__(128) void k_agg2(const float* __restrict__ b2,
                                              float* __restrict__ out) {
    int n = blockIdx.x * 4 + (threadIdx.x >> 5);
    int lane = threadIdx.x & 31;
    if (n >= N_NODES) return;
    const uint32_t* hp = (const uint32_t*)g_h2h;    // 24 uint32 per row
    float2 a = make_float2(0.f, 0.f);
    if (lane < 24) {
        uint32_t sv = hp[(size_t)n * 24 + lane];
        a = __half22float2(*(__half2*)&sv);
    }
    int e0 = g_off[n], e1 = g_off[n + 1];
    for (int e = e0; e < e1; e++) {
        int s = g_csr[e];
        if (lane < 24) {
            uint32_t v = hp[(size_t)s * 24 + lane];
            float2 f = __half22float2(*(__half2*)&v);
            a.x += f.x; a.y += f.y;
        }
    }
    if (lane < 24) {
        float dv = g_dinv[n];
        int col = lane * 2;
        out[(size_t)n * N_CLS + col] = fmaf(dv, a.x, b2[col]);
        if (col + 1 < N_CLS)
            out[(size_t)n * N_CLS + col + 1] = fmaf(dv, a.y, b2[col + 1]);
    }
}

// =====================  launch  =====================
extern "C" void kernel_launch(void* const* d_in, const int* in_sizes, int n_in,
                              void* d_out, int out_size) {
    const float* x    = (const float*)d_in[0];
    const int*   edge = (const int*)d_in[1];
    const float* W1   = (const float*)d_in[2];
    const float* b1   = (const float*)d_in[3];
    const float* W2   = (const float*)d_in[4];
    const float* b2   = (const float*)d_in[5];
    float*       out  = (float*)d_out;

    const int E = in_sizes[1] / 2;
    const int* src = edge;
    const int* dst = edge + E;

    // CSR build
    k_init      <<<(N_NODES + 255) / 256, 256>>>();
    k_count     <<<(E + 255) / 256, 256>>>(dst, E);
    k_scan_block<<<NBLK_SCAN, 256>>>();
    k_scan_bsum <<<1, 512>>>();
    k_scan_add  <<<NBLK_SCAN, 256>>>();
    k_fill      <<<(E + 255) / 256, 256>>>(src, dst, E);

    // weight prep
    int wtot = D_HID * D_IN + NC_PAD * D_HID;
    k_cvtW      <<<(wtot + 255) / 256, 256>>>(W1, W2);

    // Layer 1
    k_gemm1_mma <<<(N_NODES + 127) / 128, 256>>>(x);
    k_agg1      <<<(N_NODES + 3) / 4, 128>>>(b1);

    // Layer 2
    k_gemm2_mma <<<(N_NODES + 127) / 128, 128>>>();
    k_agg2      <<<(N_NODES + 3) / 4, 128>>>(b2, out);
}